// round 10
// baseline (speedup 1.0000x reference)
#include <cuda_runtime.h>
#include <cuda_bf16.h>
#include <mma.h>
#include <math.h>
#include <cstdint>

using namespace nvcuda;

#define BB 2
#define TT 1024
#define DD 1024
#define HH 16
#define CH 64
#define BHN (BB*HH)
#define NCH 16

// ---------------- device scratch ----------------
__device__ __align__(128) float g_logA[BHN*TT];
__device__ __align__(128) float g_cum [BHN*TT];
__device__ __align__(128) float g_gate[BHN*TT*CH];

// input hi/lo split
__device__ __align__(128) __nv_bfloat16 g_Ih[BB*TT*DD];
__device__ __align__(128) __nv_bfloat16 g_Il[BB*TT*DD];
// packed per-head projection weights [H][272][64] (0-191 XBC, 192-255 gate, 256 logA)
__device__ __align__(128) __nv_bfloat16 g_PWh[HH*272*64];
__device__ __align__(128) __nv_bfloat16 g_PWl[HH*272*64];

// bf16 hi/lo activations
__device__ __align__(128) __nv_bfloat16 g_Xh[BHN*TT*CH];
__device__ __align__(128) __nv_bfloat16 g_Xl[BHN*TT*CH];
__device__ __align__(128) __nv_bfloat16 g_Bh[BHN*TT*CH];
__device__ __align__(128) __nv_bfloat16 g_Bl[BHN*TT*CH];
__device__ __align__(128) __nv_bfloat16 g_Chh[BHN*TT*CH];
__device__ __align__(128) __nv_bfloat16 g_Cll[BHN*TT*CH];

// chunked-scan intermediates
__device__ __align__(128) float         g_P  [BHN*NCH*64*64];
__device__ __align__(128) __nv_bfloat16 g_Sth[BHN*NCH*64*64];
__device__ __align__(128) __nv_bfloat16 g_Stl[BHN*NCH*64*64];

// output GEMM operands
__device__ __align__(128) __nv_bfloat16 g_YgH[BB*TT*DD];
__device__ __align__(128) __nv_bfloat16 g_YgL[BB*TT*DD];
__device__ __align__(128) __nv_bfloat16 g_WH [DD*DD];
__device__ __align__(128) __nv_bfloat16 g_WL [DD*DD];

// ---------------- helpers ----------------
__device__ __forceinline__ uint32_t smem_u32(const void* p) {
    uint32_t a;
    asm("{ .reg .u64 t; cvta.to.shared.u64 t, %1; cvt.u32.u64 %0, t; }" : "=r"(a) : "l"(p));
    return a;
}
__device__ __forceinline__ void cp16(uint32_t dst, const void* src) {
    asm volatile("cp.async.cg.shared.global [%0], [%1], 16;" :: "r"(dst), "l"(src) : "memory");
}
#define CP_COMMIT() asm volatile("cp.async.commit_group;" ::: "memory")
#define CP_WAIT(n)  asm volatile("cp.async.wait_group %0;" :: "n"(n) : "memory")

// =================================================================================
// cvt_inp: inp fp32 -> bf16 hi/lo
// =================================================================================
__global__ __launch_bounds__(256) void cvt_inp(const float* __restrict__ inp)
{
    const int i = blockIdx.x * 256 + threadIdx.x;   // < 524288 float4s
    float4 v = ((const float4*)inp)[i];
    float x[4] = {v.x, v.y, v.z, v.w};
    __nv_bfloat16 h[4], l[4];
#pragma unroll
    for (int k = 0; k < 4; ++k) {
        h[k] = __float2bfloat16_rn(x[k]);
        l[k] = __float2bfloat16_rn(x[k] - __bfloat162float(h[k]));
    }
    ((__nv_bfloat162*)g_Ih)[i*2+0] = __halves2bfloat162(h[0], h[1]);
    ((__nv_bfloat162*)g_Ih)[i*2+1] = __halves2bfloat162(h[2], h[3]);
    ((__nv_bfloat162*)g_Il)[i*2+0] = __halves2bfloat162(l[0], l[1]);
    ((__nv_bfloat162*)g_Il)[i*2+1] = __halves2bfloat162(l[2], l[3]);
}

// =================================================================================
// cvt_w: pack per-head weights into [H][272][64] bf16 hi/lo
// =================================================================================
__global__ __launch_bounds__(256) void cvt_w(
    const float* __restrict__ W_logA, const float* __restrict__ W_XBC,
    const float* __restrict__ W_gate)
{
    const int idx = blockIdx.x * 256 + threadIdx.x;   // < 16*272*64 = 278528
    const int h   = idx / (272*64);
    const int rem = idx % (272*64);
    const int o   = rem >> 6, c = rem & 63;
    float v = 0.f;
    if (o < 192)      v = W_XBC[((size_t)h*192 + o)*64 + c];
    else if (o < 256) v = W_gate[((size_t)h*64 + (o-192))*64 + c];
    else if (o == 256) v = W_logA[h*64 + c];
    __nv_bfloat16 hi = __float2bfloat16_rn(v);
    g_PWh[idx] = hi;
    g_PWl[idx] = __float2bfloat16_rn(v - __bfloat162float(hi));
}

// =================================================================================
// proj_mma: per-head projections via wmma bf16x3. CTA = (64-row m-tile, head).
// out[m][o] = sum_c x[m][c] * W[o][c], K=64 one shot.
// 8 warps: warpM = wid&3 (16 rows), warpN = wid>>2 (col-tiles 0..8 / 9..16).
// Epilogue: bias + silu/identity -> g_X/B/C hi-lo, g_gate, g_logA.
// =================================================================================
#define PM_XT   9216                    // 64*72*2
#define PM_WOFF (2*PM_XT)               // 18432
#define PM_WT   39168                   // 272*72*2
#define PM_SMEM (PM_WOFF + 2*PM_WT)     // 96768  (S32 64x272 fp32 overlays W region)

__global__ __launch_bounds__(256) void proj_mma(
    const float* __restrict__ b_logA, const float* __restrict__ b_XBC,
    const float* __restrict__ b_gate)
{
    extern __shared__ __align__(128) char sm[];
    const uint32_t sbase = smem_u32(sm);
    __nv_bfloat16* Xh_s = (__nv_bfloat16*)(sm);
    __nv_bfloat16* Xl_s = (__nv_bfloat16*)(sm + PM_XT);
    __nv_bfloat16* Wh_s = (__nv_bfloat16*)(sm + PM_WOFF);
    __nv_bfloat16* Wl_s = (__nv_bfloat16*)(sm + PM_WOFF + PM_WT);
    float* S32 = (float*)(sm + PM_WOFF);

    const int mb  = blockIdx.x * 64;
    const int h   = blockIdx.y;
    const int tid = threadIdx.x;
    const int w = tid >> 5, warpM = w & 3, warpN = w >> 2;

    // X tiles: 2 x 64 rows x 8 cp16 = 1024 ops
#pragma unroll
    for (int s = 0; s < 4; ++s) {
        int l = tid + s*256;
        int tile = l >> 9, ww = l & 511, r = ww >> 3, q = ww & 7;
        const __nv_bfloat16* g = (tile ? g_Il : g_Ih) + (size_t)(mb + r)*DD + h*CH + q*8;
        cp16(sbase + (uint32_t)(tile*PM_XT + r*144 + q*16), g);
    }
    // W tiles: 2 x 272 rows x 8 = 4352 ops
#pragma unroll
    for (int s = 0; s < 17; ++s) {
        int l = tid + s*256;
        int tile = l / 2176, ww = l % 2176, r = ww >> 3, q = ww & 7;
        const __nv_bfloat16* g = (tile ? g_PWl : g_PWh) + ((size_t)h*272 + r)*64 + q*8;
        cp16(sbase + (uint32_t)(PM_WOFF + tile*PM_WT + r*144 + q*16), g);
    }
    CP_COMMIT();
    CP_WAIT(0);
    __syncthreads();

    const int nt0 = warpN * 9;
    const int ntN = warpN ? 8 : 9;
    wmma::fragment<wmma::accumulator,16,16,16,float> acc[9];
#pragma unroll
    for (int t = 0; t < 9; ++t) wmma::fill_fragment(acc[t], 0.f);

#pragma unroll
    for (int kk = 0; kk < 4; ++kk) {
        wmma::fragment<wmma::matrix_a,16,16,16,__nv_bfloat16,wmma::row_major> aH, aL;
        wmma::load_matrix_sync(aH, &Xh_s[(warpM*16)*72 + kk*16], 72);
        wmma::load_matrix_sync(aL, &Xl_s[(warpM*16)*72 + kk*16], 72);
        for (int t = 0; t < ntN; ++t) {
            const int nt = nt0 + t;
            wmma::fragment<wmma::matrix_b,16,16,16,__nv_bfloat16,wmma::col_major> bH, bL;
            wmma::load_matrix_sync(bH, &Wh_s[(nt*16)*72 + kk*16], 72);
            wmma::load_matrix_sync(bL, &Wl_s[(nt*16)*72 + kk*16], 72);
            wmma::mma_sync(acc[t], aH, bH, acc[t]);
            wmma::mma_sync(acc[t], aH, bL, acc[t]);
            wmma::mma_sync(acc[t], aL, bH, acc[t]);
        }
    }
    __syncthreads();   // all warps done reading W -> safe to overlay S32

    for (int t = 0; t < ntN; ++t)
        wmma::store_matrix_sync(&S32[(warpM*16)*272 + (nt0+t)*16], acc[t], 272,
                                wmma::mem_row_major);
    __syncthreads();

    // epilogue: 64 rows x 257 real outputs
    for (int idx = tid; idx < 64*257; idx += 256) {
        int r = idx / 257, o = idx % 257;
        int m  = mb + r;
        int b_ = m >> 10;
        int t  = m & (TT-1);
        int bh = b_*HH + h;
        float v = S32[r*272 + o];
        if (o < 192) {
            float z = v + b_XBC[h*192 + o];
            float s = z / (1.f + __expf(-z));
            __nv_bfloat16 hi = __float2bfloat16_rn(s);
            __nv_bfloat16 lo = __float2bfloat16_rn(s - __bfloat162float(hi));
            size_t q;
            if (o < 64)       { q = ((size_t)bh*TT + t)*CH + o;       g_Xh[q]=hi; g_Xl[q]=lo; }
            else if (o < 128) { q = ((size_t)bh*TT + t)*CH + (o-64);  g_Bh[q]=hi; g_Bl[q]=lo; }
            else              { q = ((size_t)bh*TT + t)*CH + (o-128); g_Chh[q]=hi; g_Cll[q]=lo; }
        } else if (o < 256) {
            g_gate[((size_t)bh*TT + t)*CH + (o-192)] = v + b_gate[h*CH + (o-192)];
        } else {
            g_logA[bh*TT + t] = v + b_logA[h];
        }
    }
}

// =================================================================================
// Kernel 2: inclusive cumsum (unchanged)
// =================================================================================
__global__ __launch_bounds__(256) void scan_kernel()
{
    __shared__ float s_tot[256];
    const int bh  = blockIdx.x;
    const int tid = threadIdx.x;
    const float* in = g_logA + bh*TT;

    float v0 = in[tid*4+0], v1 = in[tid*4+1], v2 = in[tid*4+2], v3 = in[tid*4+3];
    float r0 = v0, r1 = r0+v1, r2 = r1+v2, r3 = r2+v3;
    float total = r3;
    s_tot[tid] = r3;

    for (int off = 1; off < 256; off <<= 1) {
        __syncthreads();
        float add = (tid >= off) ? s_tot[tid - off] : 0.f;
        __syncthreads();
        s_tot[tid] += add;
    }
    __syncthreads();
    float excl = s_tot[tid] - total;

    float* out = g_cum + bh*TT;
    out[tid*4+0] = excl + r0;
    out[tid*4+1] = excl + r1;
    out[tid*4+2] = excl + r2;
    out[tid*4+3] = excl + r3;
}

// =================================================================================
// Kernel 3a: chunk moments P_k = B'^T @ X (unchanged)
// =================================================================================
#define KC_LDS 72
__global__ __launch_bounds__(256) void state_kernel()
{
    __shared__ __nv_bfloat16 Bp_h[64*KC_LDS], Bp_l[64*KC_LDS];
    __shared__ __nv_bfloat16 Xh_s[64*KC_LDS], Xl_s[64*KC_LDS];
    __shared__ float sc[64];

    const int k   = blockIdx.x;
    const int bh  = blockIdx.y;
    const int tid = threadIdx.x;
    const int w = tid >> 5, mrow = w & 3, nh = w >> 2;

    const uint32_t xh_b = smem_u32(Xh_s), xl_b = smem_u32(Xl_s);
#pragma unroll
    for (int s = 0; s < 4; ++s) {
        int l = tid + s*256;
        int tile = l >> 9, ww = l & 511, r = ww >> 3, q = ww & 7;
        const __nv_bfloat16* g = (tile ? g_Xl : g_Xh) + ((size_t)bh*TT + k*64 + r)*CH + q*8;
        cp16((tile ? xl_b : xh_b) + (uint32_t)(r*144 + q*16), g);
    }
    CP_COMMIT();
    if (tid < 64)
        sc[tid] = __expf(g_cum[bh*TT + k*64 + 63] - g_cum[bh*TT + k*64 + tid]);
    __syncthreads();

#pragma unroll
    for (int q = 0; q < 16; ++q) {
        int idx = tid + q*256;
        int ii = idx >> 6, jj = idx & 63;
        size_t go = ((size_t)bh*TT + k*64 + ii)*CH + jj;
        float v = (__bfloat162float(g_Bh[go]) + __bfloat162float(g_Bl[go])) * sc[ii];
        __nv_bfloat16 h = __float2bfloat16_rn(v);
        Bp_h[ii*KC_LDS + jj] = h;
        Bp_l[ii*KC_LDS + jj] = __float2bfloat16_rn(v - __bfloat162float(h));
    }
    CP_WAIT(0);
    __syncthreads();

    wmma::fragment<wmma::accumulator,16,16,16,float> pacc[2];
#pragma unroll
    for (int t2 = 0; t2 < 2; ++t2) wmma::fill_fragment(pacc[t2], 0.f);
#pragma unroll
    for (int kk = 0; kk < 4; ++kk) {
        wmma::fragment<wmma::matrix_a,16,16,16,__nv_bfloat16,wmma::col_major> aH, aL;
        wmma::load_matrix_sync(aH, &Bp_h[(kk*16)*KC_LDS + mrow*16], KC_LDS);
        wmma::load_matrix_sync(aL, &Bp_l[(kk*16)*KC_LDS + mrow*16], KC_LDS);
#pragma unroll
        for (int t2 = 0; t2 < 2; ++t2) {
            const int nt = nh*2 + t2;
            wmma::fragment<wmma::matrix_b,16,16,16,__nv_bfloat16,wmma::row_major> bH, bL;
            wmma::load_matrix_sync(bH, &Xh_s[(kk*16)*KC_LDS + nt*16], KC_LDS);
            wmma::load_matrix_sync(bL, &Xl_s[(kk*16)*KC_LDS + nt*16], KC_LDS);
            wmma::mma_sync(pacc[t2], aH, bH, pacc[t2]);
            wmma::mma_sync(pacc[t2], aH, bL, pacc[t2]);
            wmma::mma_sync(pacc[t2], aL, bH, pacc[t2]);
        }
    }
#pragma unroll
    for (int t2 = 0; t2 < 2; ++t2) {
        float* dst = g_P + ((size_t)bh*NCH + k)*4096 + (mrow*16)*64 + (nh*2+t2)*16;
        wmma::store_matrix_sync(dst, pacc[t2], 64, wmma::mem_row_major);
    }
}

// =================================================================================
// Kernel 3b: state scan — all P prefetched (MLP), decays in smem, bf16x2 stores.
// =================================================================================
__global__ __launch_bounds__(256) void scan_state()
{
    __shared__ float d[16];
    const int bh  = blockIdx.x;
    const int eb  = blockIdx.y * 512;
    const int tid = threadIdx.x;
    const int base = eb + tid*2;

    if (tid < 15) {
        float Ek = g_cum[bh*TT + tid*64 + 63];
        float Ep = (tid > 0) ? g_cum[bh*TT + tid*64 - 1] : 0.f;
        d[tid] = __expf(Ek - Ep);
    }

    float2 P[15];
#pragma unroll
    for (int k = 0; k < 15; ++k)
        P[k] = *(const float2*)&g_P[((size_t)bh*NCH + k)*4096 + base];
    __syncthreads();

    float2 S = make_float2(0.f, 0.f);
#pragma unroll
    for (int k = 0; k < 16; ++k) {
        size_t so = ((size_t)bh*NCH + k)*4096 + base;
        __nv_bfloat16 hx = __float2bfloat16_rn(S.x);
        __nv_bfloat16 hy = __float2bfloat16_rn(S.y);
        *(__nv_bfloat162*)(g_Sth + so) = __halves2bfloat162(hx, hy);
        *(__nv_bfloat162*)(g_Stl + so) = __halves2bfloat162(
            __float2bfloat16_rn(S.x - __bfloat162float(hx)),
            __float2bfloat16_rn(S.y - __bfloat162float(hy)));
        if (k < 15) {
            S.x = d[k]*S.x + P[k].x;
            S.y = d[k]*S.y + P[k].y;
        }
    }
}

// =================================================================================
// Kernel 3c: per-chunk output (unchanged from R9)
// =================================================================================
#define AC_TILE (64*KC_LDS*2)
#define AC_S32A (8*AC_TILE)
#define AC_S32B (AC_S32A + 64*68*4)
#define AC_SCI  (AC_S32B + 64*68*4)
#define AC_SMEM (AC_SCI + 2*64*4)

__global__ __launch_bounds__(256) void attn_chunk()
{
    extern __shared__ __align__(128) char sm[];
    const uint32_t sbase = smem_u32(sm);
    __nv_bfloat16* Ch  = (__nv_bfloat16*)(sm);
    __nv_bfloat16* Cl  = (__nv_bfloat16*)(sm + 1*AC_TILE);
    __nv_bfloat16* Bh  = (__nv_bfloat16*)(sm + 2*AC_TILE);
    __nv_bfloat16* Bl  = (__nv_bfloat16*)(sm + 3*AC_TILE);
    __nv_bfloat16* Xh  = (__nv_bfloat16*)(sm + 4*AC_TILE);
    __nv_bfloat16* Xl  = (__nv_bfloat16*)(sm + 5*AC_TILE);
    __nv_bfloat16* Sth = (__nv_bfloat16*)(sm + 6*AC_TILE);
    __nv_bfloat16* Stl = (__nv_bfloat16*)(sm + 7*AC_TILE);
    float* S32a = (float*)(sm + AC_S32A);
    float* S32b = (float*)(sm + AC_S32B);
    float* sCi  = (float*)(sm + AC_SCI);
    float* sCj  = sCi + 64;

    const int k   = blockIdx.x;
    const int bh  = blockIdx.y;
    const int tid = threadIdx.x;
    const int w = tid >> 5, mrow = w & 3, nh = w >> 2;

    {
        const __nv_bfloat16* act[6] = {g_Chh, g_Cll, g_Bh, g_Bl, g_Xh, g_Xl};
#pragma unroll
        for (int s = 0; s < 12; ++s) {
            int l = tid + s*256;
            int tile = l >> 9, ww = l & 511, r = ww >> 3, q = ww & 7;
            const __nv_bfloat16* g = act[tile] + ((size_t)bh*TT + k*64 + r)*CH + q*8;
            cp16(sbase + (uint32_t)(tile*AC_TILE + r*144 + q*16), g);
        }
#pragma unroll
        for (int s = 0; s < 4; ++s) {
            int l = tid + s*256;
            int tile = l >> 9, ww = l & 511, r = ww >> 3, q = ww & 7;
            const __nv_bfloat16* g = (tile ? g_Stl : g_Sth) + ((size_t)bh*NCH + k)*4096 + r*64 + q*8;
            cp16(sbase + (uint32_t)((6+tile)*AC_TILE + r*144 + q*16), g);
        }
        CP_COMMIT();
    }
    {
        const float bk = (k > 0) ? g_cum[bh*TT + k*64 - 1] : 0.f;
        if (tid < 64)  sCi[tid] = __expf(g_cum[bh*TT + k*64 + tid] - bk);
        else if (tid < 128) sCj[tid-64] = __expf(bk - g_cum[bh*TT + k*64 + (tid-64)]);
    }
    CP_WAIT(0);
    __syncthreads();

    wmma::fragment<wmma::accumulator,16,16,16,float> sacc[2];
#pragma unroll
    for (int t2 = 0; t2 < 2; ++t2) wmma::fill_fragment(sacc[t2], 0.f);
#pragma unroll
    for (int kk = 0; kk < 4; ++kk) {
        wmma::fragment<wmma::matrix_a,16,16,16,__nv_bfloat16,wmma::row_major> aH, aL;
        wmma::load_matrix_sync(aH, &Ch[(mrow*16)*KC_LDS + kk*16], KC_LDS);
        wmma::load_matrix_sync(aL, &Cl[(mrow*16)*KC_LDS + kk*16], KC_LDS);
#pragma unroll
        for (int t2 = 0; t2 < 2; ++t2) {
            const int nt = nh*2 + t2;
            wmma::fragment<wmma::matrix_b,16,16,16,__nv_bfloat16,wmma::col_major> bH, bL;
            wmma::load_matrix_sync(bH, &Bh[(nt*16)*KC_LDS + kk*16], KC_LDS);
            wmma::load_matrix_sync(bL, &Bl[(nt*16)*KC_LDS + kk*16], KC_LDS);
            wmma::mma_sync(sacc[t2], aH, bH, sacc[t2]);
            wmma::mma_sync(sacc[t2], aH, bL, sacc[t2]);
            wmma::mma_sync(sacc[t2], aL, bH, sacc[t2]);
        }
    }
#pragma unroll
    for (int t2 = 0; t2 < 2; ++t2)
        wmma::store_matrix_sync(&S32a[(mrow*16)*68 + (nh*2+t2)*16], sacc[t2], 68,
                                wmma::mem_row_major);
    __syncthreads();

#pragma unroll
    for (int q = 0; q < 16; ++q) {
        int idx = (tid & 31) + q*32;
        int ii = mrow*16 + (idx >> 5);
        int jj = nh*32 + (idx & 31);
        float v = S32a[ii*68 + jj] * sCi[ii] * sCj[jj];
        if (jj > ii) v = 0.f;
        __nv_bfloat16 h = __float2bfloat16_rn(v);
        Bh[ii*KC_LDS + jj] = h;
        Bl[ii*KC_LDS + jj] = __float2bfloat16_rn(v - __bfloat162float(h));
    }
    __syncthreads();

    wmma::fragment<wmma::accumulator,16,16,16,float> yacc[2], zacc[2];
#pragma unroll
    for (int t2 = 0; t2 < 2; ++t2) { wmma::fill_fragment(yacc[t2], 0.f); wmma::fill_fragment(zacc[t2], 0.f); }
#pragma unroll
    for (int kk = 0; kk < 4; ++kk) {
        wmma::fragment<wmma::matrix_a,16,16,16,__nv_bfloat16,wmma::row_major> aH, aL, cH, cL;
        wmma::load_matrix_sync(aH, &Bh[(mrow*16)*KC_LDS + kk*16], KC_LDS);
        wmma::load_matrix_sync(aL, &Bl[(mrow*16)*KC_LDS + kk*16], KC_LDS);
        wmma::load_matrix_sync(cH, &Ch[(mrow*16)*KC_LDS + kk*16], KC_LDS);
        wmma::load_matrix_sync(cL, &Cl[(mrow*16)*KC_LDS + kk*16], KC_LDS);
#pragma unroll
        for (int t2 = 0; t2 < 2; ++t2) {
            const int ct = nh*2 + t2;
            wmma::fragment<wmma::matrix_b,16,16,16,__nv_bfloat16,wmma::row_major> bH, bL, sH, sL;
            wmma::load_matrix_sync(bH, &Xh[(kk*16)*KC_LDS + ct*16], KC_LDS);
            wmma::load_matrix_sync(bL, &Xl[(kk*16)*KC_LDS + ct*16], KC_LDS);
            wmma::mma_sync(yacc[t2], aH, bH, yacc[t2]);
            wmma::mma_sync(yacc[t2], aH, bL, yacc[t2]);
            wmma::mma_sync(yacc[t2], aL, bH, yacc[t2]);
            wmma::load_matrix_sync(sH, &Sth[(kk*16)*KC_LDS + ct*16], KC_LDS);
            wmma::load_matrix_sync(sL, &Stl[(kk*16)*KC_LDS + ct*16], KC_LDS);
            wmma::mma_sync(zacc[t2], cH, sH, zacc[t2]);
            wmma::mma_sync(zacc[t2], cH, sL, zacc[t2]);
            wmma::mma_sync(zacc[t2], cL, sH, zacc[t2]);
        }
    }
#pragma unroll
    for (int t2 = 0; t2 < 2; ++t2) {
        wmma::store_matrix_sync(&S32a[(mrow*16)*68 + (nh*2+t2)*16], yacc[t2], 68, wmma::mem_row_major);
        wmma::store_matrix_sync(&S32b[(mrow*16)*68 + (nh*2+t2)*16], zacc[t2], 68, wmma::mem_row_major);
    }
    __syncwarp();

    const int b_ = bh >> 4, h = bh & 15;
#pragma unroll
    for (int q = 0; q < 16; ++q) {
        int idx = (tid & 31) + q*32;
        int ii = mrow*16 + (idx >> 5);
        int cc = nh*32 + (idx & 31);
        float y = S32a[ii*68 + cc] + sCi[ii] * S32b[ii*68 + cc];
        float v = y * g_gate[((size_t)bh*TT + k*64 + ii)*CH + cc];
        size_t o = ((size_t)b_*TT + k*64 + ii)*DD + h*CH + cc;
        __nv_bfloat16 hh = __float2bfloat16_rn(v);
        g_YgH[o] = hh;
        g_YgL[o] = __float2bfloat16_rn(v - __bfloat162float(hh));
    }
}

// =================================================================================
// cvt_kernel: W_out fp32 -> bf16 hi/lo (unchanged)
// =================================================================================
__global__ __launch_bounds__(256) void cvt_kernel(const float* __restrict__ W_out)
{
    const int i = blockIdx.x * 256 + threadIdx.x;
    float4 v = ((const float4*)W_out)[i];
    float x[4] = {v.x, v.y, v.z, v.w};
    __nv_bfloat16 h[4], l[4];
#pragma unroll
    for (int k = 0; k < 4; ++k) {
        h[k] = __float2bfloat16_rn(x[k]);
        l[k] = __float2bfloat16_rn(x[k] - __bfloat162float(h[k]));
    }
    ((__nv_bfloat162*)g_WH)[i*2+0] = __halves2bfloat162(h[0], h[1]);
    ((__nv_bfloat162*)g_WH)[i*2+1] = __halves2bfloat162(h[2], h[3]);
    ((__nv_bfloat162*)g_WL)[i*2+0] = __halves2bfloat162(l[0], l[1]);
    ((__nv_bfloat162*)g_WL)[i*2+1] = __halves2bfloat162(l[2], l[3]);
}

// =================================================================================
// out_gemm_wmma (unchanged from R8)
// =================================================================================
#define NCHUNK   32
#define TILE_B   10240
#define STAGE_B  (4*TILE_B)
#define BIAS_OFF (2*STAGE_B)
#define OG_SMEM  (BIAS_OFF + 16*128*4)

__global__ __launch_bounds__(256) void out_gemm_wmma(
    const float* __restrict__ b_out, float* __restrict__ out)
{
    extern __shared__ __align__(128) char smem[];
    const uint32_t sbase = smem_u32(smem);
    __nv_bfloat16* s_bf = (__nv_bfloat16*)smem;
    float* bias_s = (float*)(smem + BIAS_OFF);

    const int tid  = threadIdx.x;
    const int wid  = tid >> 5;
    const int warpM = wid & 3;
    const int warpN = wid >> 2;
    const int mb = blockIdx.x * 128;
    const int nb = blockIdx.y * 128;

    const __nv_bfloat16* __restrict__ srcs[4] = {g_YgH, g_YgL, g_WH, g_WL};

    auto issue_stage = [&](int chunk, int p) {
        const int kc = chunk * 32;
        const uint32_t sb = sbase + (uint32_t)p * STAGE_B;
#pragma unroll
        for (int s = 0; s < 8; ++s) {
            const int l = tid + s * 256;
            const int tile = l >> 9;
            const int w = l & 511;
            const int r = w >> 2;
            const int q = w & 3;
            const int grow = (tile < 2 ? mb : nb) + r;
            const __nv_bfloat16* g = srcs[tile] + (size_t)grow * DD + kc + q * 8;
            cp16(sb + tile * TILE_B + r * 80 + q * 16, g);
        }
        CP_COMMIT();
    };

    issue_stage(0, 0);

    for (int i = tid; i < 16*128; i += 256) bias_s[i] = b_out[nb + (i & 127)];
    __syncthreads();

    wmma::fragment<wmma::accumulator, 16, 16, 16, float> acc[2][4];
#pragma unroll
    for (int mt = 0; mt < 2; ++mt)
#pragma unroll
        for (int nt = 0; nt < 4; ++nt)
            wmma::load_matrix_sync(acc[mt][nt], &bias_s[warpN*64 + nt*16], 128,
                                   wmma::mem_row_major);

    for (int c = 0; c < NCHUNK; ++c) {
        const int p = c & 1;
        if (c + 1 < NCHUNK) { issue_stage(c + 1, p ^ 1); CP_WAIT(1); }
        else                { CP_WAIT(0); }
        __syncthreads();

        __nv_bfloat16* sAH = s_bf + (size_t)p * (STAGE_B/2);
        __nv_bfloat16* sAL = sAH + TILE_B/2;
        __nv_bfloat16* sBH = sAH + TILE_B;
        __nv_bfloat16* sBL = sAH + 3*(TILE_B/2);

#pragma unroll
        for (int ks = 0; ks < 2; ++ks) {
            wmma::fragment<wmma::matrix_a, 16, 16, 16, __nv_bfloat16, wmma::row_major> aH[2], aL[2];
#pragma unroll
            for (int mt = 0; mt < 2; ++mt) {
                wmma::load_matrix_sync(aH[mt], &sAH[(warpM*32 + mt*16)*40 + ks*16], 40);
                wmma::load_matrix_sync(aL[mt], &sAL[(warpM*32 + mt*16)*40 + ks*16], 40);
            }
#pragma unroll
            for (int nt = 0; nt < 4; ++nt) {
                wmma::fragment<wmma::matrix_b, 16, 16, 16, __nv_bfloat16, wmma::col_major> bH, bL;
                wmma::load_matrix_sync(bH, &sBH[(warpN*64 + nt*16)*40 + ks*16], 40);
                wmma::load_matrix_sync(bL, &sBL[(warpN*64 + nt*16)*40 + ks*16], 40);
#pragma unroll
                for (int mt = 0; mt < 2; ++mt) {
                    wmma::mma_sync(acc[mt][nt], aH[mt], bH, acc[mt][nt]);
                    wmma::mma_sync(acc[mt][nt], aH[mt], bL, acc[mt][nt]);
                    wmma::mma_sync(acc[mt][nt], aL[mt], bH, acc[mt][nt]);
                }
            }
        }
        __syncthreads();
    }

#pragma unroll
    for (int mt = 0; mt < 2; ++mt)
#pragma unroll
        for (int nt = 0; nt < 4; ++nt) {
            float* dst = out + (size_t)(mb + warpM*32 + mt*16) * DD + nb + warpN*64 + nt*16;
            wmma::store_matrix_sync(dst, acc[mt][nt], DD, wmma::mem_row_major);
        }
}

// =================================================================================
extern "C" void kernel_launch(void* const* d_in, const int* in_sizes, int n_in,
                              void* d_out, int out_size)
{
    const float* inp    = (const float*)d_in[0];
    const float* W_logA = (const float*)d_in[1];
    const float* b_logA = (const float*)d_in[2];
    const float* W_XBC  = (const float*)d_in[3];
    const float* b_XBC  = (const float*)d_in[4];
    const float* W_gate = (const float*)d_in[5];
    const float* b_gate = (const float*)d_in[6];
    const float* W_out  = (const float*)d_in[7];
    const float* b_out  = (const float*)d_in[8];
    float* out = (float*)d_out;

    cvt_inp<<<2048, 256>>>(inp);
    cvt_w<<<1088, 256>>>(W_logA, W_XBC, W_gate);
    cvt_kernel<<<1024, 256>>>(W_out);

    cudaFuncSetAttribute(proj_mma, cudaFuncAttributeMaxDynamicSharedMemorySize, PM_SMEM);
    proj_mma<<<dim3(32, 16), 256, PM_SMEM>>>(b_logA, b_XBC, b_gate);

    scan_kernel<<<32, 256>>>();

    state_kernel<<<dim3(NCH-1, BHN), 256>>>();
    scan_state<<<dim3(BHN, 8), 256>>>();

    cudaFuncSetAttribute(attn_chunk, cudaFuncAttributeMaxDynamicSharedMemorySize, AC_SMEM);
    attn_chunk<<<dim3(NCH, BHN), 256, AC_SMEM>>>();

    cudaFuncSetAttribute(out_gemm_wmma, cudaFuncAttributeMaxDynamicSharedMemorySize, OG_SMEM);
    out_gemm_wmma<<<dim3(16, 8), 256, OG_SMEM>>>(b_out, out);
}

// round 11
// speedup vs baseline: 1.0333x; 1.0333x over previous
#include <cuda_runtime.h>
#include <cuda_bf16.h>
#include <mma.h>
#include <math.h>
#include <cstdint>

using namespace nvcuda;

#define BB 2
#define TT 1024
#define DD 1024
#define HH 16
#define CH 64
#define BHN (BB*HH)
#define NCH 16

// ---------------- device scratch ----------------
__device__ __align__(128) float g_logA[BHN*TT];
__device__ __align__(128) float g_cum [BHN*TT];
__device__ __align__(128) float g_gate[BHN*TT*CH];

// bf16 hi/lo activations (written directly by proj_kernel)
__device__ __align__(128) __nv_bfloat16 g_Xh[BHN*TT*CH];
__device__ __align__(128) __nv_bfloat16 g_Xl[BHN*TT*CH];
__device__ __align__(128) __nv_bfloat16 g_Bh[BHN*TT*CH];
__device__ __align__(128) __nv_bfloat16 g_Bl[BHN*TT*CH];
__device__ __align__(128) __nv_bfloat16 g_Chh[BHN*TT*CH];
__device__ __align__(128) __nv_bfloat16 g_Cll[BHN*TT*CH];

// chunked-scan intermediates
__device__ __align__(128) float         g_P  [BHN*NCH*64*64];
__device__ __align__(128) __nv_bfloat16 g_Sth[BHN*NCH*64*64];
__device__ __align__(128) __nv_bfloat16 g_Stl[BHN*NCH*64*64];

// output GEMM operands
__device__ __align__(128) __nv_bfloat16 g_YgH[BB*TT*DD];
__device__ __align__(128) __nv_bfloat16 g_YgL[BB*TT*DD];
__device__ __align__(128) __nv_bfloat16 g_WH [DD*DD];
__device__ __align__(128) __nv_bfloat16 g_WL [DD*DD];

// ---------------- helpers ----------------
__device__ __forceinline__ uint32_t smem_u32(const void* p) {
    uint32_t a;
    asm("{ .reg .u64 t; cvta.to.shared.u64 t, %1; cvt.u32.u64 %0, t; }" : "=r"(a) : "l"(p));
    return a;
}
__device__ __forceinline__ void cp16(uint32_t dst, const void* src) {
    asm volatile("cp.async.cg.shared.global [%0], [%1], 16;" :: "r"(dst), "l"(src) : "memory");
}
#define CP_COMMIT() asm volatile("cp.async.commit_group;" ::: "memory")
#define CP_WAIT(n)  asm volatile("cp.async.wait_group %0;" :: "n"(n) : "memory")

// =================================================================================
// Kernel 1: fused per-head projections (fp32 FFMA, emits bf16 hi/lo — R9 version)
// =================================================================================
__global__ __launch_bounds__(128) void proj_kernel(
    const float* __restrict__ inp,
    const float* __restrict__ W_logA, const float* __restrict__ b_logA,
    const float* __restrict__ W_XBC,  const float* __restrict__ b_XBC,
    const float* __restrict__ W_gate, const float* __restrict__ b_gate)
{
    __shared__ float As[64*68];
    __shared__ float Ws[64*68];

    const int h     = blockIdx.z;
    const int mbase = blockIdx.x * 64;
    const int obase = blockIdx.y * 64;
    const int tid   = threadIdx.x;

    for (int l4 = tid; l4 < 64*16; l4 += 128) {
        int r = l4 >> 4, c4 = l4 & 15;
        float4 v = *(const float4*)&inp[(size_t)(mbase + r) * DD + h*CH + c4*4];
        *(float4*)&As[r*68 + c4*4] = v;
    }
    for (int l4 = tid; l4 < 64*16; l4 += 128) {
        int r = l4 >> 4, c4 = l4 & 15;
        int o = obase + r;
        float4 v = make_float4(0.f, 0.f, 0.f, 0.f);
        if (o == 0)        v = *(const float4*)&W_logA[h*CH + c4*4];
        else if (o <= 192) v = *(const float4*)&W_XBC[((h*192) + (o-1))*CH + c4*4];
        else if (o < 257)  v = *(const float4*)&W_gate[((h*CH) + (o-193))*CH + c4*4];
        *(float4*)&Ws[r*68 + c4*4] = v;
    }
    __syncthreads();

    const int ty = tid >> 4, tx = tid & 15;
    float acc[8][4];
#pragma unroll
    for (int i = 0; i < 8; ++i)
#pragma unroll
        for (int j = 0; j < 4; ++j) acc[i][j] = 0.f;

#pragma unroll
    for (int k4 = 0; k4 < 16; ++k4) {
        float4 a[8], b[4];
#pragma unroll
        for (int i = 0; i < 8; ++i) a[i] = *(float4*)&As[(ty + 8*i)*68 + k4*4];
#pragma unroll
        for (int j = 0; j < 4; ++j) b[j] = *(float4*)&Ws[(tx + 16*j)*68 + k4*4];
#pragma unroll
        for (int i = 0; i < 8; ++i)
#pragma unroll
            for (int j = 0; j < 4; ++j) {
                acc[i][j] += a[i].x*b[j].x;
                acc[i][j] += a[i].y*b[j].y;
                acc[i][j] += a[i].z*b[j].z;
                acc[i][j] += a[i].w*b[j].w;
            }
    }

#pragma unroll
    for (int i = 0; i < 8; ++i) {
#pragma unroll
        for (int j = 0; j < 4; ++j) {
            int o = obase + tx + 16*j;
            if (o >= 257) continue;
            int m  = mbase + ty + 8*i;
            int b_ = m >> 10;
            int t  = m & (TT-1);
            int bh = b_*HH + h;
            float v = acc[i][j];
            if (o == 0) {
                g_logA[bh*TT + t] = v + b_logA[h];
            } else if (o <= 192) {
                int oo = o - 1;
                float z = v + b_XBC[h*192 + oo];
                float s = z / (1.f + __expf(-z));
                __nv_bfloat16 hi = __float2bfloat16_rn(s);
                __nv_bfloat16 lo = __float2bfloat16_rn(s - __bfloat162float(hi));
                size_t idx;
                if (oo < 64)       { idx = ((size_t)bh*TT + t)*CH + oo;       g_Xh[idx]=hi; g_Xl[idx]=lo; }
                else if (oo < 128) { idx = ((size_t)bh*TT + t)*CH + (oo-64);  g_Bh[idx]=hi; g_Bl[idx]=lo; }
                else               { idx = ((size_t)bh*TT + t)*CH + (oo-128); g_Chh[idx]=hi; g_Cll[idx]=lo; }
            } else {
                int oo = o - 193;
                g_gate[((size_t)bh*TT + t)*CH + oo] = v + b_gate[h*CH + oo];
            }
        }
    }
}

// =================================================================================
// Kernel 2: inclusive cumsum (unchanged)
// =================================================================================
__global__ __launch_bounds__(256) void scan_kernel()
{
    __shared__ float s_tot[256];
    const int bh  = blockIdx.x;
    const int tid = threadIdx.x;
    const float* in = g_logA + bh*TT;

    float v0 = in[tid*4+0], v1 = in[tid*4+1], v2 = in[tid*4+2], v3 = in[tid*4+3];
    float r0 = v0, r1 = r0+v1, r2 = r1+v2, r3 = r2+v3;
    float total = r3;
    s_tot[tid] = r3;

    for (int off = 1; off < 256; off <<= 1) {
        __syncthreads();
        float add = (tid >= off) ? s_tot[tid - off] : 0.f;
        __syncthreads();
        s_tot[tid] += add;
    }
    __syncthreads();
    float excl = s_tot[tid] - total;

    float* out = g_cum + bh*TT;
    out[tid*4+0] = excl + r0;
    out[tid*4+1] = excl + r1;
    out[tid*4+2] = excl + r2;
    out[tid*4+3] = excl + r3;
}

// =================================================================================
// Kernel 3a: chunk moments P_k = B'^T @ X (unchanged)
// =================================================================================
#define KC_LDS 72
__global__ __launch_bounds__(256) void state_kernel()
{
    __shared__ __nv_bfloat16 Bp_h[64*KC_LDS], Bp_l[64*KC_LDS];
    __shared__ __nv_bfloat16 Xh_s[64*KC_LDS], Xl_s[64*KC_LDS];
    __shared__ float sc[64];

    const int k   = blockIdx.x;
    const int bh  = blockIdx.y;
    const int tid = threadIdx.x;
    const int w = tid >> 5, mrow = w & 3, nh = w >> 2;

    const uint32_t xh_b = smem_u32(Xh_s), xl_b = smem_u32(Xl_s);
#pragma unroll
    for (int s = 0; s < 4; ++s) {
        int l = tid + s*256;
        int tile = l >> 9, ww = l & 511, r = ww >> 3, q = ww & 7;
        const __nv_bfloat16* g = (tile ? g_Xl : g_Xh) + ((size_t)bh*TT + k*64 + r)*CH + q*8;
        cp16((tile ? xl_b : xh_b) + (uint32_t)(r*144 + q*16), g);
    }
    CP_COMMIT();
    if (tid < 64)
        sc[tid] = __expf(g_cum[bh*TT + k*64 + 63] - g_cum[bh*TT + k*64 + tid]);
    __syncthreads();

#pragma unroll
    for (int q = 0; q < 16; ++q) {
        int idx = tid + q*256;
        int ii = idx >> 6, jj = idx & 63;
        size_t go = ((size_t)bh*TT + k*64 + ii)*CH + jj;
        float v = (__bfloat162float(g_Bh[go]) + __bfloat162float(g_Bl[go])) * sc[ii];
        __nv_bfloat16 h = __float2bfloat16_rn(v);
        Bp_h[ii*KC_LDS + jj] = h;
        Bp_l[ii*KC_LDS + jj] = __float2bfloat16_rn(v - __bfloat162float(h));
    }
    CP_WAIT(0);
    __syncthreads();

    wmma::fragment<wmma::accumulator,16,16,16,float> pacc[2];
#pragma unroll
    for (int t2 = 0; t2 < 2; ++t2) wmma::fill_fragment(pacc[t2], 0.f);
#pragma unroll
    for (int kk = 0; kk < 4; ++kk) {
        wmma::fragment<wmma::matrix_a,16,16,16,__nv_bfloat16,wmma::col_major> aH, aL;
        wmma::load_matrix_sync(aH, &Bp_h[(kk*16)*KC_LDS + mrow*16], KC_LDS);
        wmma::load_matrix_sync(aL, &Bp_l[(kk*16)*KC_LDS + mrow*16], KC_LDS);
#pragma unroll
        for (int t2 = 0; t2 < 2; ++t2) {
            const int nt = nh*2 + t2;
            wmma::fragment<wmma::matrix_b,16,16,16,__nv_bfloat16,wmma::row_major> bH, bL;
            wmma::load_matrix_sync(bH, &Xh_s[(kk*16)*KC_LDS + nt*16], KC_LDS);
            wmma::load_matrix_sync(bL, &Xl_s[(kk*16)*KC_LDS + nt*16], KC_LDS);
            wmma::mma_sync(pacc[t2], aH, bH, pacc[t2]);
            wmma::mma_sync(pacc[t2], aH, bL, pacc[t2]);
            wmma::mma_sync(pacc[t2], aL, bH, pacc[t2]);
        }
    }
#pragma unroll
    for (int t2 = 0; t2 < 2; ++t2) {
        float* dst = g_P + ((size_t)bh*NCH + k)*4096 + (mrow*16)*64 + (nh*2+t2)*16;
        wmma::store_matrix_sync(dst, pacc[t2], 64, wmma::mem_row_major);
    }
}

// =================================================================================
// Kernel 3b: state scan — prefetched P (MLP=30), decays in smem, bf16x2 stores.
// =================================================================================
__global__ __launch_bounds__(256) void scan_state()
{
    __shared__ float d[16];
    const int bh  = blockIdx.x;
    const int eb  = blockIdx.y * 512;
    const int tid = threadIdx.x;
    const int base = eb + tid*2;

    if (tid < 15) {
        float Ek = g_cum[bh*TT + tid*64 + 63];
        float Ep = (tid > 0) ? g_cum[bh*TT + tid*64 - 1] : 0.f;
        d[tid] = __expf(Ek - Ep);
    }

    float2 P[15];
#pragma unroll
    for (int k = 0; k < 15; ++k)
        P[k] = *(const float2*)&g_P[((size_t)bh*NCH + k)*4096 + base];
    __syncthreads();

    float2 S = make_float2(0.f, 0.f);
#pragma unroll
    for (int k = 0; k < 16; ++k) {
        size_t so = ((size_t)bh*NCH + k)*4096 + base;
        __nv_bfloat16 hx = __float2bfloat16_rn(S.x);
        __nv_bfloat16 hy = __float2bfloat16_rn(S.y);
        *(__nv_bfloat162*)(g_Sth + so) = __halves2bfloat162(hx, hy);
        *(__nv_bfloat162*)(g_Stl + so) = __halves2bfloat162(
            __float2bfloat16_rn(S.x - __bfloat162float(hx)),
            __float2bfloat16_rn(S.y - __bfloat162float(hy)));
        if (k < 15) {
            S.x = d[k]*S.x + P[k].x;
            S.y = d[k]*S.y + P[k].y;
        }
    }
}

// =================================================================================
// Kernel 3c: per-chunk output (unchanged from R9)
// =================================================================================
#define AC_TILE (64*KC_LDS*2)
#define AC_S32A (8*AC_TILE)
#define AC_S32B (AC_S32A + 64*68*4)
#define AC_SCI  (AC_S32B + 64*68*4)
#define AC_SMEM (AC_SCI + 2*64*4)

__global__ __launch_bounds__(256) void attn_chunk()
{
    extern __shared__ __align__(128) char sm[];
    const uint32_t sbase = smem_u32(sm);
    __nv_bfloat16* Ch  = (__nv_bfloat16*)(sm);
    __nv_bfloat16* Cl  = (__nv_bfloat16*)(sm + 1*AC_TILE);
    __nv_bfloat16* Bh  = (__nv_bfloat16*)(sm + 2*AC_TILE);
    __nv_bfloat16* Bl  = (__nv_bfloat16*)(sm + 3*AC_TILE);
    __nv_bfloat16* Xh  = (__nv_bfloat16*)(sm + 4*AC_TILE);
    __nv_bfloat16* Xl  = (__nv_bfloat16*)(sm + 5*AC_TILE);
    __nv_bfloat16* Sth = (__nv_bfloat16*)(sm + 6*AC_TILE);
    __nv_bfloat16* Stl = (__nv_bfloat16*)(sm + 7*AC_TILE);
    float* S32a = (float*)(sm + AC_S32A);
    float* S32b = (float*)(sm + AC_S32B);
    float* sCi  = (float*)(sm + AC_SCI);
    float* sCj  = sCi + 64;

    const int k   = blockIdx.x;
    const int bh  = blockIdx.y;
    const int tid = threadIdx.x;
    const int w = tid >> 5, mrow = w & 3, nh = w >> 2;

    {
        const __nv_bfloat16* act[6] = {g_Chh, g_Cll, g_Bh, g_Bl, g_Xh, g_Xl};
#pragma unroll
        for (int s = 0; s < 12; ++s) {
            int l = tid + s*256;
            int tile = l >> 9, ww = l & 511, r = ww >> 3, q = ww & 7;
            const __nv_bfloat16* g = act[tile] + ((size_t)bh*TT + k*64 + r)*CH + q*8;
            cp16(sbase + (uint32_t)(tile*AC_TILE + r*144 + q*16), g);
        }
#pragma unroll
        for (int s = 0; s < 4; ++s) {
            int l = tid + s*256;
            int tile = l >> 9, ww = l & 511, r = ww >> 3, q = ww & 7;
            const __nv_bfloat16* g = (tile ? g_Stl : g_Sth) + ((size_t)bh*NCH + k)*4096 + r*64 + q*8;
            cp16(sbase + (uint32_t)((6+tile)*AC_TILE + r*144 + q*16), g);
        }
        CP_COMMIT();
    }
    {
        const float bk = (k > 0) ? g_cum[bh*TT + k*64 - 1] : 0.f;
        if (tid < 64)  sCi[tid] = __expf(g_cum[bh*TT + k*64 + tid] - bk);
        else if (tid < 128) sCj[tid-64] = __expf(bk - g_cum[bh*TT + k*64 + (tid-64)]);
    }
    CP_WAIT(0);
    __syncthreads();

    wmma::fragment<wmma::accumulator,16,16,16,float> sacc[2];
#pragma unroll
    for (int t2 = 0; t2 < 2; ++t2) wmma::fill_fragment(sacc[t2], 0.f);
#pragma unroll
    for (int kk = 0; kk < 4; ++kk) {
        wmma::fragment<wmma::matrix_a,16,16,16,__nv_bfloat16,wmma::row_major> aH, aL;
        wmma::load_matrix_sync(aH, &Ch[(mrow*16)*KC_LDS + kk*16], KC_LDS);
        wmma::load_matrix_sync(aL, &Cl[(mrow*16)*KC_LDS + kk*16], KC_LDS);
#pragma unroll
        for (int t2 = 0; t2 < 2; ++t2) {
            const int nt = nh*2 + t2;
            wmma::fragment<wmma::matrix_b,16,16,16,__nv_bfloat16,wmma::col_major> bH, bL;
            wmma::load_matrix_sync(bH, &Bh[(nt*16)*KC_LDS + kk*16], KC_LDS);
            wmma::load_matrix_sync(bL, &Bl[(nt*16)*KC_LDS + kk*16], KC_LDS);
            wmma::mma_sync(sacc[t2], aH, bH, sacc[t2]);
            wmma::mma_sync(sacc[t2], aH, bL, sacc[t2]);
            wmma::mma_sync(sacc[t2], aL, bH, sacc[t2]);
        }
    }
#pragma unroll
    for (int t2 = 0; t2 < 2; ++t2)
        wmma::store_matrix_sync(&S32a[(mrow*16)*68 + (nh*2+t2)*16], sacc[t2], 68,
                                wmma::mem_row_major);
    __syncthreads();

#pragma unroll
    for (int q = 0; q < 16; ++q) {
        int idx = (tid & 31) + q*32;
        int ii = mrow*16 + (idx >> 5);
        int jj = nh*32 + (idx & 31);
        float v = S32a[ii*68 + jj] * sCi[ii] * sCj[jj];
        if (jj > ii) v = 0.f;
        __nv_bfloat16 h = __float2bfloat16_rn(v);
        Bh[ii*KC_LDS + jj] = h;
        Bl[ii*KC_LDS + jj] = __float2bfloat16_rn(v - __bfloat162float(h));
    }
    __syncthreads();

    wmma::fragment<wmma::accumulator,16,16,16,float> yacc[2], zacc[2];
#pragma unroll
    for (int t2 = 0; t2 < 2; ++t2) { wmma::fill_fragment(yacc[t2], 0.f); wmma::fill_fragment(zacc[t2], 0.f); }
#pragma unroll
    for (int kk = 0; kk < 4; ++kk) {
        wmma::fragment<wmma::matrix_a,16,16,16,__nv_bfloat16,wmma::row_major> aH, aL, cH, cL;
        wmma::load_matrix_sync(aH, &Bh[(mrow*16)*KC_LDS + kk*16], KC_LDS);
        wmma::load_matrix_sync(aL, &Bl[(mrow*16)*KC_LDS + kk*16], KC_LDS);
        wmma::load_matrix_sync(cH, &Ch[(mrow*16)*KC_LDS + kk*16], KC_LDS);
        wmma::load_matrix_sync(cL, &Cl[(mrow*16)*KC_LDS + kk*16], KC_LDS);
#pragma unroll
        for (int t2 = 0; t2 < 2; ++t2) {
            const int ct = nh*2 + t2;
            wmma::fragment<wmma::matrix_b,16,16,16,__nv_bfloat16,wmma::row_major> bH, bL, sH, sL;
            wmma::load_matrix_sync(bH, &Xh[(kk*16)*KC_LDS + ct*16], KC_LDS);
            wmma::load_matrix_sync(bL, &Xl[(kk*16)*KC_LDS + ct*16], KC_LDS);
            wmma::mma_sync(yacc[t2], aH, bH, yacc[t2]);
            wmma::mma_sync(yacc[t2], aH, bL, yacc[t2]);
            wmma::mma_sync(yacc[t2], aL, bH, yacc[t2]);
            wmma::load_matrix_sync(sH, &Sth[(kk*16)*KC_LDS + ct*16], KC_LDS);
            wmma::load_matrix_sync(sL, &Stl[(kk*16)*KC_LDS + ct*16], KC_LDS);
            wmma::mma_sync(zacc[t2], cH, sH, zacc[t2]);
            wmma::mma_sync(zacc[t2], cH, sL, zacc[t2]);
            wmma::mma_sync(zacc[t2], cL, sH, zacc[t2]);
        }
    }
#pragma unroll
    for (int t2 = 0; t2 < 2; ++t2) {
        wmma::store_matrix_sync(&S32a[(mrow*16)*68 + (nh*2+t2)*16], yacc[t2], 68, wmma::mem_row_major);
        wmma::store_matrix_sync(&S32b[(mrow*16)*68 + (nh*2+t2)*16], zacc[t2], 68, wmma::mem_row_major);
    }
    __syncwarp();

    const int b_ = bh >> 4, h = bh & 15;
#pragma unroll
    for (int q = 0; q < 16; ++q) {
        int idx = (tid & 31) + q*32;
        int ii = mrow*16 + (idx >> 5);
        int cc = nh*32 + (idx & 31);
        float y = S32a[ii*68 + cc] + sCi[ii] * S32b[ii*68 + cc];
        float v = y * g_gate[((size_t)bh*TT + k*64 + ii)*CH + cc];
        size_t o = ((size_t)b_*TT + k*64 + ii)*DD + h*CH + cc;
        __nv_bfloat16 hh = __float2bfloat16_rn(v);
        g_YgH[o] = hh;
        g_YgL[o] = __float2bfloat16_rn(v - __bfloat162float(hh));
    }
}

// =================================================================================
// cvt_kernel: W_out fp32 -> bf16 hi/lo
// =================================================================================
__global__ __launch_bounds__(256) void cvt_kernel(const float* __restrict__ W_out)
{
    const int i = blockIdx.x * 256 + threadIdx.x;
    float4 v = ((const float4*)W_out)[i];
    float x[4] = {v.x, v.y, v.z, v.w};
    __nv_bfloat16 h[4], l[4];
#pragma unroll
    for (int k = 0; k < 4; ++k) {
        h[k] = __float2bfloat16_rn(x[k]);
        l[k] = __float2bfloat16_rn(x[k] - __bfloat162float(h[k]));
    }
    ((__nv_bfloat162*)g_WH)[i*2+0] = __halves2bfloat162(h[0], h[1]);
    ((__nv_bfloat162*)g_WH)[i*2+1] = __halves2bfloat162(h[2], h[3]);
    ((__nv_bfloat162*)g_WL)[i*2+0] = __halves2bfloat162(l[0], l[1]);
    ((__nv_bfloat162*)g_WL)[i*2+1] = __halves2bfloat162(l[2], l[3]);
}

// =================================================================================
// out_gemm_wmma (unchanged)
// =================================================================================
#define NCHUNK   32
#define TILE_B   10240
#define STAGE_B  (4*TILE_B)
#define BIAS_OFF (2*STAGE_B)
#define OG_SMEM  (BIAS_OFF + 16*128*4)

__global__ __launch_bounds__(256) void out_gemm_wmma(
    const float* __restrict__ b_out, float* __restrict__ out)
{
    extern __shared__ __align__(128) char smem[];
    const uint32_t sbase = smem_u32(smem);
    __nv_bfloat16* s_bf = (__nv_bfloat16*)smem;
    float* bias_s = (float*)(smem + BIAS_OFF);

    const int tid  = threadIdx.x;
    const int wid  = tid >> 5;
    const int warpM = wid & 3;
    const int warpN = wid >> 2;
    const int mb = blockIdx.x * 128;
    const int nb = blockIdx.y * 128;

    const __nv_bfloat16* __restrict__ srcs[4] = {g_YgH, g_YgL, g_WH, g_WL};

    auto issue_stage = [&](int chunk, int p) {
        const int kc = chunk * 32;
        const uint32_t sb = sbase + (uint32_t)p * STAGE_B;
#pragma unroll
        for (int s = 0; s < 8; ++s) {
            const int l = tid + s * 256;
            const int tile = l >> 9;
            const int w = l & 511;
            const int r = w >> 2;
            const int q = w & 3;
            const int grow = (tile < 2 ? mb : nb) + r;
            const __nv_bfloat16* g = srcs[tile] + (size_t)grow * DD + kc + q * 8;
            cp16(sb + tile * TILE_B + r * 80 + q * 16, g);
        }
        CP_COMMIT();
    };

    issue_stage(0, 0);

    for (int i = tid; i < 16*128; i += 256) bias_s[i] = b_out[nb + (i & 127)];
    __syncthreads();

    wmma::fragment<wmma::accumulator, 16, 16, 16, float> acc[2][4];
#pragma unroll
    for (int mt = 0; mt < 2; ++mt)
#pragma unroll
        for (int nt = 0; nt < 4; ++nt)
            wmma::load_matrix_sync(acc[mt][nt], &bias_s[warpN*64 + nt*16], 128,
                                   wmma::mem_row_major);

    for (int c = 0; c < NCHUNK; ++c) {
        const int p = c & 1;
        if (c + 1 < NCHUNK) { issue_stage(c + 1, p ^ 1); CP_WAIT(1); }
        else                { CP_WAIT(0); }
        __syncthreads();

        __nv_bfloat16* sAH = s_bf + (size_t)p * (STAGE_B/2);
        __nv_bfloat16* sAL = sAH + TILE_B/2;
        __nv_bfloat16* sBH = sAH + TILE_B;
        __nv_bfloat16* sBL = sAH + 3*(TILE_B/2);

#pragma unroll
        for (int ks = 0; ks < 2; ++ks) {
            wmma::fragment<wmma::matrix_a, 16, 16, 16, __nv_bfloat16, wmma::row_major> aH[2], aL[2];
#pragma unroll
            for (int mt = 0; mt < 2; ++mt) {
                wmma::load_matrix_sync(aH[mt], &sAH[(warpM*32 + mt*16)*40 + ks*16], 40);
                wmma::load_matrix_sync(aL[mt], &sAL[(warpM*32 + mt*16)*40 + ks*16], 40);
            }
#pragma unroll
            for (int nt = 0; nt < 4; ++nt) {
                wmma::fragment<wmma::matrix_b, 16, 16, 16, __nv_bfloat16, wmma::col_major> bH, bL;
                wmma::load_matrix_sync(bH, &sBH[(warpN*64 + nt*16)*40 + ks*16], 40);
                wmma::load_matrix_sync(bL, &sBL[(warpN*64 + nt*16)*40 + ks*16], 40);
#pragma unroll
                for (int mt = 0; mt < 2; ++mt) {
                    wmma::mma_sync(acc[mt][nt], aH[mt], bH, acc[mt][nt]);
                    wmma::mma_sync(acc[mt][nt], aH[mt], bL, acc[mt][nt]);
                    wmma::mma_sync(acc[mt][nt], aL[mt], bH, acc[mt][nt]);
                }
            }
        }
        __syncthreads();
    }

#pragma unroll
    for (int mt = 0; mt < 2; ++mt)
#pragma unroll
        for (int nt = 0; nt < 4; ++nt) {
            float* dst = out + (size_t)(mb + warpM*32 + mt*16) * DD + nb + warpN*64 + nt*16;
            wmma::store_matrix_sync(dst, acc[mt][nt], DD, wmma::mem_row_major);
        }
}

// =================================================================================
extern "C" void kernel_launch(void* const* d_in, const int* in_sizes, int n_in,
                              void* d_out, int out_size)
{
    const float* inp    = (const float*)d_in[0];
    const float* W_logA = (const float*)d_in[1];
    const float* b_logA = (const float*)d_in[2];
    const float* W_XBC  = (const float*)d_in[3];
    const float* b_XBC  = (const float*)d_in[4];
    const float* W_gate = (const float*)d_in[5];
    const float* b_gate = (const float*)d_in[6];
    const float* W_out  = (const float*)d_in[7];
    const float* b_out  = (const float*)d_in[8];
    float* out = (float*)d_out;

    proj_kernel<<<dim3(32, 5, 16), 128>>>(inp, W_logA, b_logA, W_XBC, b_XBC, W_gate, b_gate);
    scan_kernel<<<32, 256>>>();

    state_kernel<<<dim3(NCH-1, BHN), 256>>>();
    scan_state<<<dim3(BHN, 8), 256>>>();

    cudaFuncSetAttribute(attn_chunk, cudaFuncAttributeMaxDynamicSharedMemorySize, AC_SMEM);
    attn_chunk<<<dim3(NCH, BHN), 256, AC_SMEM>>>();

    cvt_kernel<<<1024, 256>>>(W_out);

    cudaFuncSetAttribute(out_gemm_wmma, cudaFuncAttributeMaxDynamicSharedMemorySize, OG_SMEM);
    out_gemm_wmma<<<dim3(16, 8), 256, OG_SMEM>>>(b_out, out);
}

// round 12
// speedup vs baseline: 1.0739x; 1.0393x over previous
#include <cuda_runtime.h>
#include <cuda_bf16.h>
#include <mma.h>
#include <math.h>
#include <cstdint>

using namespace nvcuda;

#define BB 2
#define TT 1024
#define DD 1024
#define HH 16
#define CH 64
#define BHN (BB*HH)
#define NCH 16

// ---------------- device scratch ----------------
__device__ __align__(128) float g_cum [BHN*TT];
__device__ __align__(128) float g_gate[BHN*TT*CH];

// bf16 hi/lo activations (written directly by proj_kernel)
__device__ __align__(128) __nv_bfloat16 g_Xh[BHN*TT*CH];
__device__ __align__(128) __nv_bfloat16 g_Xl[BHN*TT*CH];
__device__ __align__(128) __nv_bfloat16 g_Bh[BHN*TT*CH];
__device__ __align__(128) __nv_bfloat16 g_Bl[BHN*TT*CH];
__device__ __align__(128) __nv_bfloat16 g_Chh[BHN*TT*CH];
__device__ __align__(128) __nv_bfloat16 g_Cll[BHN*TT*CH];

// chunked-scan intermediates
__device__ __align__(128) float         g_P  [BHN*NCH*64*64];
__device__ __align__(128) __nv_bfloat16 g_Sth[BHN*NCH*64*64];
__device__ __align__(128) __nv_bfloat16 g_Stl[BHN*NCH*64*64];

// output GEMM operands
__device__ __align__(128) __nv_bfloat16 g_YgH[BB*TT*DD];
__device__ __align__(128) __nv_bfloat16 g_YgL[BB*TT*DD];
__device__ __align__(128) __nv_bfloat16 g_WH [DD*DD];
__device__ __align__(128) __nv_bfloat16 g_WL [DD*DD];

// ---------------- helpers ----------------
__device__ __forceinline__ uint32_t smem_u32(const void* p) {
    uint32_t a;
    asm("{ .reg .u64 t; cvta.to.shared.u64 t, %1; cvt.u32.u64 %0, t; }" : "=r"(a) : "l"(p));
    return a;
}
__device__ __forceinline__ void cp16(uint32_t dst, const void* src) {
    asm volatile("cp.async.cg.shared.global [%0], [%1], 16;" :: "r"(dst), "l"(src) : "memory");
}
#define CP_COMMIT() asm volatile("cp.async.commit_group;" ::: "memory")
#define CP_WAIT(n)  asm volatile("cp.async.wait_group %0;" :: "n"(n) : "memory")

// =================================================================================
// Kernel 1: fused per-head projections (fp32 FFMA). logA REMOVED: 256 outputs
// = exactly 4 o-tiles (0-191 XBC, 192-255 gate). grid (32, 4, 16).
// =================================================================================
__global__ __launch_bounds__(128) void proj_kernel(
    const float* __restrict__ inp,
    const float* __restrict__ W_XBC,  const float* __restrict__ b_XBC,
    const float* __restrict__ W_gate, const float* __restrict__ b_gate)
{
    __shared__ float As[64*68];
    __shared__ float Ws[64*68];

    const int h     = blockIdx.z;
    const int mbase = blockIdx.x * 64;
    const int obase = blockIdx.y * 64;
    const int tid   = threadIdx.x;

    for (int l4 = tid; l4 < 64*16; l4 += 128) {
        int r = l4 >> 4, c4 = l4 & 15;
        float4 v = *(const float4*)&inp[(size_t)(mbase + r) * DD + h*CH + c4*4];
        *(float4*)&As[r*68 + c4*4] = v;
    }
    for (int l4 = tid; l4 < 64*16; l4 += 128) {
        int r = l4 >> 4, c4 = l4 & 15;
        int o = obase + r;
        float4 v;
        if (o < 192) v = *(const float4*)&W_XBC[((size_t)(h*192) + o)*CH + c4*4];
        else         v = *(const float4*)&W_gate[((size_t)(h*CH) + (o-192))*CH + c4*4];
        *(float4*)&Ws[r*68 + c4*4] = v;
    }
    __syncthreads();

    const int ty = tid >> 4, tx = tid & 15;
    float acc[8][4];
#pragma unroll
    for (int i = 0; i < 8; ++i)
#pragma unroll
        for (int j = 0; j < 4; ++j) acc[i][j] = 0.f;

#pragma unroll
    for (int k4 = 0; k4 < 16; ++k4) {
        float4 a[8], b[4];
#pragma unroll
        for (int i = 0; i < 8; ++i) a[i] = *(float4*)&As[(ty + 8*i)*68 + k4*4];
#pragma unroll
        for (int j = 0; j < 4; ++j) b[j] = *(float4*)&Ws[(tx + 16*j)*68 + k4*4];
#pragma unroll
        for (int i = 0; i < 8; ++i)
#pragma unroll
            for (int j = 0; j < 4; ++j) {
                acc[i][j] += a[i].x*b[j].x;
                acc[i][j] += a[i].y*b[j].y;
                acc[i][j] += a[i].z*b[j].z;
                acc[i][j] += a[i].w*b[j].w;
            }
    }

#pragma unroll
    for (int i = 0; i < 8; ++i) {
#pragma unroll
        for (int j = 0; j < 4; ++j) {
            int o  = obase + tx + 16*j;
            int m  = mbase + ty + 8*i;
            int b_ = m >> 10;
            int t  = m & (TT-1);
            int bh = b_*HH + h;
            float v = acc[i][j];
            if (o < 192) {
                float z = v + b_XBC[h*192 + o];
                float s = z / (1.f + __expf(-z));
                __nv_bfloat16 hi = __float2bfloat16_rn(s);
                __nv_bfloat16 lo = __float2bfloat16_rn(s - __bfloat162float(hi));
                size_t idx;
                if (o < 64)       { idx = ((size_t)bh*TT + t)*CH + o;       g_Xh[idx]=hi; g_Xl[idx]=lo; }
                else if (o < 128) { idx = ((size_t)bh*TT + t)*CH + (o-64);  g_Bh[idx]=hi; g_Bl[idx]=lo; }
                else              { idx = ((size_t)bh*TT + t)*CH + (o-128); g_Chh[idx]=hi; g_Cll[idx]=lo; }
            } else {
                g_gate[((size_t)bh*TT + t)*CH + (o-192)] = v + b_gate[h*CH + (o-192)];
            }
        }
    }
}

// =================================================================================
// Kernel 2: fused logA GEMV + inclusive cumsum. Per block (bh): logA[t] =
// dot(W_logA[h], inp[b,t,h*64:]) + b_logA[h], then Blelloch-style block scan.
// =================================================================================
__global__ __launch_bounds__(256) void scan_kernel(
    const float* __restrict__ inp,
    const float* __restrict__ W_logA, const float* __restrict__ b_logA)
{
    __shared__ float s_tot[256];
    __shared__ float w[64];
    const int bh  = blockIdx.x;
    const int b_  = bh >> 4, h = bh & 15;
    const int tid = threadIdx.x;

    if (tid < 64) w[tid] = W_logA[h*CH + tid];
    __syncthreads();
    const float bA = b_logA[h];

    float v[4];
#pragma unroll
    for (int j = 0; j < 4; ++j) {
        const int t = tid*4 + j;
        const float4* row = (const float4*)&inp[((size_t)b_*TT + t)*DD + h*CH];
        float dot = 0.f;
#pragma unroll
        for (int c4 = 0; c4 < 16; ++c4) {
            float4 x = row[c4];
            dot += x.x*w[c4*4+0] + x.y*w[c4*4+1] + x.z*w[c4*4+2] + x.w*w[c4*4+3];
        }
        v[j] = dot + bA;
    }

    float r0 = v[0], r1 = r0+v[1], r2 = r1+v[2], r3 = r2+v[3];
    float total = r3;
    s_tot[tid] = r3;

    for (int off = 1; off < 256; off <<= 1) {
        __syncthreads();
        float add = (tid >= off) ? s_tot[tid - off] : 0.f;
        __syncthreads();
        s_tot[tid] += add;
    }
    __syncthreads();
    float excl = s_tot[tid] - total;

    float* out = g_cum + bh*TT;
    out[tid*4+0] = excl + r0;
    out[tid*4+1] = excl + r1;
    out[tid*4+2] = excl + r2;
    out[tid*4+3] = excl + r3;
}

// =================================================================================
// Kernel 3a: chunk moments P_k = B'^T @ X (unchanged)
// =================================================================================
#define KC_LDS 72
__global__ __launch_bounds__(256) void state_kernel()
{
    __shared__ __nv_bfloat16 Bp_h[64*KC_LDS], Bp_l[64*KC_LDS];
    __shared__ __nv_bfloat16 Xh_s[64*KC_LDS], Xl_s[64*KC_LDS];
    __shared__ float sc[64];

    const int k   = blockIdx.x;
    const int bh  = blockIdx.y;
    const int tid = threadIdx.x;
    const int w = tid >> 5, mrow = w & 3, nh = w >> 2;

    const uint32_t xh_b = smem_u32(Xh_s), xl_b = smem_u32(Xl_s);
#pragma unroll
    for (int s = 0; s < 4; ++s) {
        int l = tid + s*256;
        int tile = l >> 9, ww = l & 511, r = ww >> 3, q = ww & 7;
        const __nv_bfloat16* g = (tile ? g_Xl : g_Xh) + ((size_t)bh*TT + k*64 + r)*CH + q*8;
        cp16((tile ? xl_b : xh_b) + (uint32_t)(r*144 + q*16), g);
    }
    CP_COMMIT();
    if (tid < 64)
        sc[tid] = __expf(g_cum[bh*TT + k*64 + 63] - g_cum[bh*TT + k*64 + tid]);
    __syncthreads();

#pragma unroll
    for (int q = 0; q < 16; ++q) {
        int idx = tid + q*256;
        int ii = idx >> 6, jj = idx & 63;
        size_t go = ((size_t)bh*TT + k*64 + ii)*CH + jj;
        float v = (__bfloat162float(g_Bh[go]) + __bfloat162float(g_Bl[go])) * sc[ii];
        __nv_bfloat16 h = __float2bfloat16_rn(v);
        Bp_h[ii*KC_LDS + jj] = h;
        Bp_l[ii*KC_LDS + jj] = __float2bfloat16_rn(v - __bfloat162float(h));
    }
    CP_WAIT(0);
    __syncthreads();

    wmma::fragment<wmma::accumulator,16,16,16,float> pacc[2];
#pragma unroll
    for (int t2 = 0; t2 < 2; ++t2) wmma::fill_fragment(pacc[t2], 0.f);
#pragma unroll
    for (int kk = 0; kk < 4; ++kk) {
        wmma::fragment<wmma::matrix_a,16,16,16,__nv_bfloat16,wmma::col_major> aH, aL;
        wmma::load_matrix_sync(aH, &Bp_h[(kk*16)*KC_LDS + mrow*16], KC_LDS);
        wmma::load_matrix_sync(aL, &Bp_l[(kk*16)*KC_LDS + mrow*16], KC_LDS);
#pragma unroll
        for (int t2 = 0; t2 < 2; ++t2) {
            const int nt = nh*2 + t2;
            wmma::fragment<wmma::matrix_b,16,16,16,__nv_bfloat16,wmma::row_major> bH, bL;
            wmma::load_matrix_sync(bH, &Xh_s[(kk*16)*KC_LDS + nt*16], KC_LDS);
            wmma::load_matrix_sync(bL, &Xl_s[(kk*16)*KC_LDS + nt*16], KC_LDS);
            wmma::mma_sync(pacc[t2], aH, bH, pacc[t2]);
            wmma::mma_sync(pacc[t2], aH, bL, pacc[t2]);
            wmma::mma_sync(pacc[t2], aL, bH, pacc[t2]);
        }
    }
#pragma unroll
    for (int t2 = 0; t2 < 2; ++t2) {
        float* dst = g_P + ((size_t)bh*NCH + k)*4096 + (mrow*16)*64 + (nh*2+t2)*16;
        wmma::store_matrix_sync(dst, pacc[t2], 64, wmma::mem_row_major);
    }
}

// =================================================================================
// Kernel 3b: state scan (prefetched, unchanged from R11)
// =================================================================================
__global__ __launch_bounds__(256) void scan_state()
{
    __shared__ float d[16];
    const int bh  = blockIdx.x;
    const int eb  = blockIdx.y * 512;
    const int tid = threadIdx.x;
    const int base = eb + tid*2;

    if (tid < 15) {
        float Ek = g_cum[bh*TT + tid*64 + 63];
        float Ep = (tid > 0) ? g_cum[bh*TT + tid*64 - 1] : 0.f;
        d[tid] = __expf(Ek - Ep);
    }

    float2 P[15];
#pragma unroll
    for (int k = 0; k < 15; ++k)
        P[k] = *(const float2*)&g_P[((size_t)bh*NCH + k)*4096 + base];
    __syncthreads();

    float2 S = make_float2(0.f, 0.f);
#pragma unroll
    for (int k = 0; k < 16; ++k) {
        size_t so = ((size_t)bh*NCH + k)*4096 + base;
        __nv_bfloat16 hx = __float2bfloat16_rn(S.x);
        __nv_bfloat16 hy = __float2bfloat16_rn(S.y);
        *(__nv_bfloat162*)(g_Sth + so) = __halves2bfloat162(hx, hy);
        *(__nv_bfloat162*)(g_Stl + so) = __halves2bfloat162(
            __float2bfloat16_rn(S.x - __bfloat162float(hx)),
            __float2bfloat16_rn(S.y - __bfloat162float(hy)));
        if (k < 15) {
            S.x = d[k]*S.x + P[k].x;
            S.y = d[k]*S.y + P[k].y;
        }
    }
}

// =================================================================================
// Kernel 3c: per-chunk output (unchanged from R9/R11)
// =================================================================================
#define AC_TILE (64*KC_LDS*2)
#define AC_S32A (8*AC_TILE)
#define AC_S32B (AC_S32A + 64*68*4)
#define AC_SCI  (AC_S32B + 64*68*4)
#define AC_SMEM (AC_SCI + 2*64*4)

__global__ __launch_bounds__(256) void attn_chunk()
{
    extern __shared__ __align__(128) char sm[];
    const uint32_t sbase = smem_u32(sm);
    __nv_bfloat16* Ch  = (__nv_bfloat16*)(sm);
    __nv_bfloat16* Cl  = (__nv_bfloat16*)(sm + 1*AC_TILE);
    __nv_bfloat16* Bh  = (__nv_bfloat16*)(sm + 2*AC_TILE);
    __nv_bfloat16* Bl  = (__nv_bfloat16*)(sm + 3*AC_TILE);
    __nv_bfloat16* Xh  = (__nv_bfloat16*)(sm + 4*AC_TILE);
    __nv_bfloat16* Xl  = (__nv_bfloat16*)(sm + 5*AC_TILE);
    __nv_bfloat16* Sth = (__nv_bfloat16*)(sm + 6*AC_TILE);
    __nv_bfloat16* Stl = (__nv_bfloat16*)(sm + 7*AC_TILE);
    float* S32a = (float*)(sm + AC_S32A);
    float* S32b = (float*)(sm + AC_S32B);
    float* sCi  = (float*)(sm + AC_SCI);
    float* sCj  = sCi + 64;

    const int k   = blockIdx.x;
    const int bh  = blockIdx.y;
    const int tid = threadIdx.x;
    const int w = tid >> 5, mrow = w & 3, nh = w >> 2;

    {
        const __nv_bfloat16* act[6] = {g_Chh, g_Cll, g_Bh, g_Bl, g_Xh, g_Xl};
#pragma unroll
        for (int s = 0; s < 12; ++s) {
            int l = tid + s*256;
            int tile = l >> 9, ww = l & 511, r = ww >> 3, q = ww & 7;
            const __nv_bfloat16* g = act[tile] + ((size_t)bh*TT + k*64 + r)*CH + q*8;
            cp16(sbase + (uint32_t)(tile*AC_TILE + r*144 + q*16), g);
        }
#pragma unroll
        for (int s = 0; s < 4; ++s) {
            int l = tid + s*256;
            int tile = l >> 9, ww = l & 511, r = ww >> 3, q = ww & 7;
            const __nv_bfloat16* g = (tile ? g_Stl : g_Sth) + ((size_t)bh*NCH + k)*4096 + r*64 + q*8;
            cp16(sbase + (uint32_t)((6+tile)*AC_TILE + r*144 + q*16), g);
        }
        CP_COMMIT();
    }
    {
        const float bk = (k > 0) ? g_cum[bh*TT + k*64 - 1] : 0.f;
        if (tid < 64)  sCi[tid] = __expf(g_cum[bh*TT + k*64 + tid] - bk);
        else if (tid < 128) sCj[tid-64] = __expf(bk - g_cum[bh*TT + k*64 + (tid-64)]);
    }
    CP_WAIT(0);
    __syncthreads();

    wmma::fragment<wmma::accumulator,16,16,16,float> sacc[2];
#pragma unroll
    for (int t2 = 0; t2 < 2; ++t2) wmma::fill_fragment(sacc[t2], 0.f);
#pragma unroll
    for (int kk = 0; kk < 4; ++kk) {
        wmma::fragment<wmma::matrix_a,16,16,16,__nv_bfloat16,wmma::row_major> aH, aL;
        wmma::load_matrix_sync(aH, &Ch[(mrow*16)*KC_LDS + kk*16], KC_LDS);
        wmma::load_matrix_sync(aL, &Cl[(mrow*16)*KC_LDS + kk*16], KC_LDS);
#pragma unroll
        for (int t2 = 0; t2 < 2; ++t2) {
            const int nt = nh*2 + t2;
            wmma::fragment<wmma::matrix_b,16,16,16,__nv_bfloat16,wmma::col_major> bH, bL;
            wmma::load_matrix_sync(bH, &Bh[(nt*16)*KC_LDS + kk*16], KC_LDS);
            wmma::load_matrix_sync(bL, &Bl[(nt*16)*KC_LDS + kk*16], KC_LDS);
            wmma::mma_sync(sacc[t2], aH, bH, sacc[t2]);
            wmma::mma_sync(sacc[t2], aH, bL, sacc[t2]);
            wmma::mma_sync(sacc[t2], aL, bH, sacc[t2]);
        }
    }
#pragma unroll
    for (int t2 = 0; t2 < 2; ++t2)
        wmma::store_matrix_sync(&S32a[(mrow*16)*68 + (nh*2+t2)*16], sacc[t2], 68,
                                wmma::mem_row_major);
    __syncthreads();

#pragma unroll
    for (int q = 0; q < 16; ++q) {
        int idx = (tid & 31) + q*32;
        int ii = mrow*16 + (idx >> 5);
        int jj = nh*32 + (idx & 31);
        float v = S32a[ii*68 + jj] * sCi[ii] * sCj[jj];
        if (jj > ii) v = 0.f;
        __nv_bfloat16 h = __float2bfloat16_rn(v);
        Bh[ii*KC_LDS + jj] = h;
        Bl[ii*KC_LDS + jj] = __float2bfloat16_rn(v - __bfloat162float(h));
    }
    __syncthreads();

    wmma::fragment<wmma::accumulator,16,16,16,float> yacc[2], zacc[2];
#pragma unroll
    for (int t2 = 0; t2 < 2; ++t2) { wmma::fill_fragment(yacc[t2], 0.f); wmma::fill_fragment(zacc[t2], 0.f); }
#pragma unroll
    for (int kk = 0; kk < 4; ++kk) {
        wmma::fragment<wmma::matrix_a,16,16,16,__nv_bfloat16,wmma::row_major> aH, aL, cH, cL;
        wmma::load_matrix_sync(aH, &Bh[(mrow*16)*KC_LDS + kk*16], KC_LDS);
        wmma::load_matrix_sync(aL, &Bl[(mrow*16)*KC_LDS + kk*16], KC_LDS);
        wmma::load_matrix_sync(cH, &Ch[(mrow*16)*KC_LDS + kk*16], KC_LDS);
        wmma::load_matrix_sync(cL, &Cl[(mrow*16)*KC_LDS + kk*16], KC_LDS);
#pragma unroll
        for (int t2 = 0; t2 < 2; ++t2) {
            const int ct = nh*2 + t2;
            wmma::fragment<wmma::matrix_b,16,16,16,__nv_bfloat16,wmma::row_major> bH, bL, sH, sL;
            wmma::load_matrix_sync(bH, &Xh[(kk*16)*KC_LDS + ct*16], KC_LDS);
            wmma::load_matrix_sync(bL, &Xl[(kk*16)*KC_LDS + ct*16], KC_LDS);
            wmma::mma_sync(yacc[t2], aH, bH, yacc[t2]);
            wmma::mma_sync(yacc[t2], aH, bL, yacc[t2]);
            wmma::mma_sync(yacc[t2], aL, bH, yacc[t2]);
            wmma::load_matrix_sync(sH, &Sth[(kk*16)*KC_LDS + ct*16], KC_LDS);
            wmma::load_matrix_sync(sL, &Stl[(kk*16)*KC_LDS + ct*16], KC_LDS);
            wmma::mma_sync(zacc[t2], cH, sH, zacc[t2]);
            wmma::mma_sync(zacc[t2], cH, sL, zacc[t2]);
            wmma::mma_sync(zacc[t2], cL, sH, zacc[t2]);
        }
    }
#pragma unroll
    for (int t2 = 0; t2 < 2; ++t2) {
        wmma::store_matrix_sync(&S32a[(mrow*16)*68 + (nh*2+t2)*16], yacc[t2], 68, wmma::mem_row_major);
        wmma::store_matrix_sync(&S32b[(mrow*16)*68 + (nh*2+t2)*16], zacc[t2], 68, wmma::mem_row_major);
    }
    __syncwarp();

    const int b_ = bh >> 4, h = bh & 15;
#pragma unroll
    for (int q = 0; q < 16; ++q) {
        int idx = (tid & 31) + q*32;
        int ii = mrow*16 + (idx >> 5);
        int cc = nh*32 + (idx & 31);
        float y = S32a[ii*68 + cc] + sCi[ii] * S32b[ii*68 + cc];
        float v = y * g_gate[((size_t)bh*TT + k*64 + ii)*CH + cc];
        size_t o = ((size_t)b_*TT + k*64 + ii)*DD + h*CH + cc;
        __nv_bfloat16 hh = __float2bfloat16_rn(v);
        g_YgH[o] = hh;
        g_YgL[o] = __float2bfloat16_rn(v - __bfloat162float(hh));
    }
}

// =================================================================================
// cvt_kernel: W_out fp32 -> bf16 hi/lo (unchanged)
// =================================================================================
__global__ __launch_bounds__(256) void cvt_kernel(const float* __restrict__ W_out)
{
    const int i = blockIdx.x * 256 + threadIdx.x;
    float4 v = ((const float4*)W_out)[i];
    float x[4] = {v.x, v.y, v.z, v.w};
    __nv_bfloat16 h[4], l[4];
#pragma unroll
    for (int k = 0; k < 4; ++k) {
        h[k] = __float2bfloat16_rn(x[k]);
        l[k] = __float2bfloat16_rn(x[k] - __bfloat162float(h[k]));
    }
    ((__nv_bfloat162*)g_WH)[i*2+0] = __halves2bfloat162(h[0], h[1]);
    ((__nv_bfloat162*)g_WH)[i*2+1] = __halves2bfloat162(h[2], h[3]);
    ((__nv_bfloat162*)g_WL)[i*2+0] = __halves2bfloat162(l[0], l[1]);
    ((__nv_bfloat162*)g_WL)[i*2+1] = __halves2bfloat162(l[2], l[3]);
}

// =================================================================================
// out_gemm_wmma: 512 threads / 16 warps (warp tile 32x32) for latency hiding.
// Same 128x128 CTA tile, K-chunk 32, 2-stage cp.async double buffer.
// =================================================================================
#define NCHUNK   32
#define TILE_B   10240
#define STAGE_B  (4*TILE_B)
#define BIAS_OFF (2*STAGE_B)
#define OG_SMEM  (BIAS_OFF + 16*128*4)

__global__ __launch_bounds__(512) void out_gemm_wmma(
    const float* __restrict__ b_out, float* __restrict__ out)
{
    extern __shared__ __align__(128) char smem[];
    const uint32_t sbase = smem_u32(smem);
    __nv_bfloat16* s_bf = (__nv_bfloat16*)smem;
    float* bias_s = (float*)(smem + BIAS_OFF);

    const int tid  = threadIdx.x;
    const int wid  = tid >> 5;
    const int warpM = wid & 3;        // 4 m-groups of 32 rows
    const int warpN = wid >> 2;       // 4 n-groups of 32 cols
    const int mb = blockIdx.x * 128;
    const int nb = blockIdx.y * 128;

    const __nv_bfloat16* __restrict__ srcs[4] = {g_YgH, g_YgL, g_WH, g_WL};

    auto issue_stage = [&](int chunk, int p) {
        const int kc = chunk * 32;
        const uint32_t sb = sbase + (uint32_t)p * STAGE_B;
#pragma unroll
        for (int s = 0; s < 4; ++s) {
            const int l = tid + s * 512;
            const int tile = l >> 9;
            const int w = l & 511;
            const int r = w >> 2;
            const int q = w & 3;
            const int grow = (tile < 2 ? mb : nb) + r;
            const __nv_bfloat16* g = srcs[tile] + (size_t)grow * DD + kc + q * 8;
            cp16(sb + tile * TILE_B + r * 80 + q * 16, g);
        }
        CP_COMMIT();
    };

    issue_stage(0, 0);

    for (int i = tid; i < 16*128; i += 512) bias_s[i] = b_out[nb + (i & 127)];
    __syncthreads();

    wmma::fragment<wmma::accumulator, 16, 16, 16, float> acc[2][2];
#pragma unroll
    for (int mt = 0; mt < 2; ++mt)
#pragma unroll
        for (int nt = 0; nt < 2; ++nt)
            wmma::load_matrix_sync(acc[mt][nt], &bias_s[warpN*32 + nt*16], 128,
                                   wmma::mem_row_major);

    for (int c = 0; c < NCHUNK; ++c) {
        const int p = c & 1;
        if (c + 1 < NCHUNK) { issue_stage(c + 1, p ^ 1); CP_WAIT(1); }
        else                { CP_WAIT(0); }
        __syncthreads();

        __nv_bfloat16* sAH = s_bf + (size_t)p * (STAGE_B/2);
        __nv_bfloat16* sAL = sAH + TILE_B/2;
        __nv_bfloat16* sBH = sAH + TILE_B;
        __nv_bfloat16* sBL = sAH + 3*(TILE_B/2);

#pragma unroll
        for (int ks = 0; ks < 2; ++ks) {
            wmma::fragment<wmma::matrix_a, 16, 16, 16, __nv_bfloat16, wmma::row_major> aH[2], aL[2];
#pragma unroll
            for (int mt = 0; mt < 2; ++mt) {
                wmma::load_matrix_sync(aH[mt], &sAH[(warpM*32 + mt*16)*40 + ks*16], 40);
                wmma::load_matrix_sync(aL[mt], &sAL[(warpM*32 + mt*16)*40 + ks*16], 40);
            }
#pragma unroll
            for (int nt = 0; nt < 2; ++nt) {
                wmma::fragment<wmma::matrix_b, 16, 16, 16, __nv_bfloat16, wmma::col_major> bH, bL;
                wmma::load_matrix_sync(bH, &sBH[(warpN*32 + nt*16)*40 + ks*16], 40);
                wmma::load_matrix_sync(bL, &sBL[(warpN*32 + nt*16)*40 + ks*16], 40);
#pragma unroll
                for (int mt = 0; mt < 2; ++mt) {
                    wmma::mma_sync(acc[mt][nt], aH[mt], bH, acc[mt][nt]);
                    wmma::mma_sync(acc[mt][nt], aH[mt], bL, acc[mt][nt]);
                    wmma::mma_sync(acc[mt][nt], aL[mt], bH, acc[mt][nt]);
                }
            }
        }
        __syncthreads();
    }

#pragma unroll
    for (int mt = 0; mt < 2; ++mt)
#pragma unroll
        for (int nt = 0; nt < 2; ++nt) {
            float* dst = out + (size_t)(mb + warpM*32 + mt*16) * DD + nb + warpN*32 + nt*16;
            wmma::store_matrix_sync(dst, acc[mt][nt], DD, wmma::mem_row_major);
        }
}

// =================================================================================
extern "C" void kernel_launch(void* const* d_in, const int* in_sizes, int n_in,
                              void* d_out, int out_size)
{
    const float* inp    = (const float*)d_in[0];
    const float* W_logA = (const float*)d_in[1];
    const float* b_logA = (const float*)d_in[2];
    const float* W_XBC  = (const float*)d_in[3];
    const float* b_XBC  = (const float*)d_in[4];
    const float* W_gate = (const float*)d_in[5];
    const float* b_gate = (const float*)d_in[6];
    const float* W_out  = (const float*)d_in[7];
    const float* b_out  = (const float*)d_in[8];
    float* out = (float*)d_out;

    proj_kernel<<<dim3(32, 4, 16), 128>>>(inp, W_XBC, b_XBC, W_gate, b_gate);
    scan_kernel<<<32, 256>>>(inp, W_logA, b_logA);

    state_kernel<<<dim3(NCH-1, BHN), 256>>>();
    scan_state<<<dim3(BHN, 8), 256>>>();

    cudaFuncSetAttribute(attn_chunk, cudaFuncAttributeMaxDynamicSharedMemorySize, AC_SMEM);
    attn_chunk<<<dim3(NCH, BHN), 256, AC_SMEM>>>();

    cvt_kernel<<<1024, 256>>>(W_out);

    cudaFuncSetAttribute(out_gemm_wmma, cudaFuncAttributeMaxDynamicSharedMemorySize, OG_SMEM);
    out_gemm_wmma<<<dim3(16, 8), 512, OG_SMEM>>>(b_out, out);
}